// round 1
// baseline (speedup 1.0000x reference)
#include <cuda_runtime.h>
#include <math.h>

#define N_NODES 100000
#define N_EDGES 800000
#define HCDIM   128
#define C_DIM   64
#define N_CLS   40
#define EPS_F   1e-16f

// ---------------- static device scratch (allocation-free) ----------------
__device__ __align__(16) float g_h0[(size_t)N_NODES * HCDIM];
__device__ __align__(16) float g_h1[(size_t)N_NODES * HCDIM];
__device__ __align__(16) float g_t [(size_t)N_NODES * C_DIM];
__device__ int g_deg[N_NODES];
__device__ int g_rowptr[N_NODES + 1];
__device__ int g_cursor[N_NODES];
__device__ int g_csrc[N_EDGES];

// ---------------- CSR build ----------------
__global__ void zero_deg_kernel() {
    int i = blockIdx.x * blockDim.x + threadIdx.x;
    if (i < N_NODES) g_deg[i] = 0;
}

__global__ void count_deg_kernel(const int* __restrict__ dst) {
    int e = blockIdx.x * blockDim.x + threadIdx.x;
    if (e < N_EDGES) atomicAdd(&g_deg[dst[e]], 1);
}

// single-block chunked exclusive scan over g_deg -> g_rowptr, g_cursor
__global__ void scan_kernel() {
    __shared__ int warp_sums[32];
    __shared__ int sCarry;
    const int tid  = threadIdx.x;       // 1024 threads
    const int lane = tid & 31;
    const int wid  = tid >> 5;
    if (tid == 0) sCarry = 0;
    __syncthreads();
    for (int base = 0; base < N_NODES; base += 1024) {
        int idx = base + tid;
        int v = (idx < N_NODES) ? g_deg[idx] : 0;
        int incl = v;
        #pragma unroll
        for (int d = 1; d < 32; d <<= 1) {
            int t = __shfl_up_sync(0xffffffffu, incl, d);
            if (lane >= d) incl += t;
        }
        if (lane == 31) warp_sums[wid] = incl;
        __syncthreads();
        if (wid == 0) {
            int s = warp_sums[lane];
            #pragma unroll
            for (int d = 1; d < 32; d <<= 1) {
                int t = __shfl_up_sync(0xffffffffu, s, d);
                if (lane >= d) s += t;
            }
            warp_sums[lane] = s;
        }
        __syncthreads();
        int carry = sCarry;
        int woff  = (wid > 0) ? warp_sums[wid - 1] : 0;
        int excl  = carry + woff + incl - v;
        if (idx < N_NODES) { g_rowptr[idx] = excl; g_cursor[idx] = excl; }
        __syncthreads();                       // everyone done reading sCarry/warp_sums
        if (tid == 0) sCarry = carry + warp_sums[31];
        __syncthreads();
    }
    if (tid == 0) g_rowptr[N_NODES] = N_EDGES;
}

__global__ void scatter_kernel(const int* __restrict__ src, const int* __restrict__ dst) {
    int e = blockIdx.x * blockDim.x + threadIdx.x;
    if (e < N_EDGES) {
        int d   = dst[e];
        int pos = atomicAdd(&g_cursor[d], 1);
        g_csrc[pos] = src[e];
    }
}

// ---------------- SGEMM: Out[N, BN] = A[N,128] @ W[BN,128]^T + bias ----------------
template <int BN, int TN>
__global__ void sgemm_bias(const float* __restrict__ A, const float* __restrict__ W,
                           const float* __restrict__ bias, float* __restrict__ Out) {
    constexpr int K  = 128;
    constexpr int BM = 128;
    constexpr int BK = 8;
    constexpr int TM = 8;
    __shared__ float As[BK][BM];
    __shared__ float Bs[BK][BN];

    const int tid = threadIdx.x;          // 256 threads
    const int tr  = tid >> 4;             // 0..15 -> row group
    const int tc  = tid & 15;             // 0..15 -> col group
    const int rowBase = blockIdx.x * BM;

    float acc[TM][TN];
    #pragma unroll
    for (int i = 0; i < TM; i++)
        #pragma unroll
        for (int j = 0; j < TN; j++) acc[i][j] = 0.f;

    for (int k0 = 0; k0 < K; k0 += BK) {
        // A tile: 128 rows x 8 k  (float4 per thread)
        {
            int r  = tid >> 1;
            int kk = (tid & 1) * 4;
            int grow = rowBase + r;
            float4 v = make_float4(0.f, 0.f, 0.f, 0.f);
            if (grow < N_NODES)
                v = *(const float4*)(A + (size_t)grow * K + k0 + kk);
            As[kk + 0][r] = v.x; As[kk + 1][r] = v.y;
            As[kk + 2][r] = v.z; As[kk + 3][r] = v.w;
        }
        // B tile: BN cols x 8 k  (W is [BN, 128] row-major)
        {
            if (BN == 128) {
                int c  = tid >> 1;
                int kk = (tid & 1) * 4;
                float4 v = *(const float4*)(W + (size_t)c * K + k0 + kk);
                Bs[kk + 0][c] = v.x; Bs[kk + 1][c] = v.y;
                Bs[kk + 2][c] = v.z; Bs[kk + 3][c] = v.w;
            } else {
                if (tid < 2 * BN) {
                    int c  = tid >> 1;
                    int kk = (tid & 1) * 4;
                    float4 v = *(const float4*)(W + (size_t)c * K + k0 + kk);
                    Bs[kk + 0][c] = v.x; Bs[kk + 1][c] = v.y;
                    Bs[kk + 2][c] = v.z; Bs[kk + 3][c] = v.w;
                }
            }
        }
        __syncthreads();
        #pragma unroll
        for (int kk = 0; kk < BK; kk++) {
            float ra[TM], rb[TN];
            #pragma unroll
            for (int i = 0; i < TM; i++) ra[i] = As[kk][tr * TM + i];
            #pragma unroll
            for (int j = 0; j < TN; j++) rb[j] = Bs[kk][tc * TN + j];
            #pragma unroll
            for (int i = 0; i < TM; i++)
                #pragma unroll
                for (int j = 0; j < TN; j++)
                    acc[i][j] += ra[i] * rb[j];
        }
        __syncthreads();
    }

    float bv[TN];
    #pragma unroll
    for (int j = 0; j < TN; j++) bv[j] = bias[tc * TN + j];

    #pragma unroll
    for (int i = 0; i < TM; i++) {
        int grow = rowBase + tr * TM + i;
        if (grow < N_NODES) {
            #pragma unroll
            for (int j = 0; j < TN; j += 4) {
                float4 o;
                o.x = acc[i][j + 0] + bv[j + 0];
                o.y = acc[i][j + 1] + bv[j + 1];
                o.z = acc[i][j + 2] + bv[j + 2];
                o.w = acc[i][j + 3] + bv[j + 3];
                *(float4*)(Out + (size_t)grow * BN + tc * TN + j) = o;
            }
        }
    }
}

// ---------------- GAT aggregation: warp per dst node ----------------
// att(e) = exp(al*h[src] - max_src(al*h[src])) / (sum + eps); out = relu(sum att*h[src])
__global__ void gat_agg(const float* __restrict__ h, const float* __restrict__ al,
                        float* __restrict__ out) {
    const int warpsPerBlock = blockDim.x >> 5;
    const int node = blockIdx.x * warpsPerBlock + (threadIdx.x >> 5);
    if (node >= N_NODES) return;
    const int lane = threadIdx.x & 31;

    const float4 a4 = *(const float4*)(al + lane * 4);
    const int beg = g_rowptr[node];
    const int end = g_rowptr[node + 1];

    float4 m4 = make_float4(-INFINITY, -INFINITY, -INFINITY, -INFINITY);
    for (int base = beg; base < end; base += 32) {
        int cnt = min(32, end - base);
        int s = (lane < cnt) ? g_csrc[base + lane] : 0;
        for (int i = 0; i < cnt; i++) {
            int src = __shfl_sync(0xffffffffu, s, i);
            float4 v = *(const float4*)(h + (size_t)src * HCDIM + lane * 4);
            m4.x = fmaxf(m4.x, a4.x * v.x);
            m4.y = fmaxf(m4.y, a4.y * v.y);
            m4.z = fmaxf(m4.z, a4.z * v.z);
            m4.w = fmaxf(m4.w, a4.w * v.w);
        }
    }

    float4 S   = make_float4(0.f, 0.f, 0.f, 0.f);
    float4 acc = make_float4(0.f, 0.f, 0.f, 0.f);
    for (int base = beg; base < end; base += 32) {
        int cnt = min(32, end - base);
        int s = (lane < cnt) ? g_csrc[base + lane] : 0;
        for (int i = 0; i < cnt; i++) {
            int src = __shfl_sync(0xffffffffu, s, i);
            float4 v = *(const float4*)(h + (size_t)src * HCDIM + lane * 4);
            float wx = __expf(a4.x * v.x - m4.x);
            float wy = __expf(a4.y * v.y - m4.y);
            float wz = __expf(a4.z * v.z - m4.z);
            float ww = __expf(a4.w * v.w - m4.w);
            S.x += wx; S.y += wy; S.z += wz; S.w += ww;
            acc.x += wx * v.x; acc.y += wy * v.y;
            acc.z += wz * v.z; acc.w += ww * v.w;
        }
    }

    float4 o;
    o.x = fmaxf(acc.x / (S.x + EPS_F), 0.f);
    o.y = fmaxf(acc.y / (S.y + EPS_F), 0.f);
    o.z = fmaxf(acc.z / (S.z + EPS_F), 0.f);
    o.w = fmaxf(acc.w / (S.w + EPS_F), 0.f);
    *(float4*)(out + (size_t)node * HCDIM + lane * 4) = o;
}

// ---------------- head: logits = t[N,64] @ Wp2[40,64]^T + bp2; log_softmax ----------------
__global__ void proj2_kernel(const float* __restrict__ Wp2, const float* __restrict__ bp2,
                             float* __restrict__ out) {
    __shared__ float w2[N_CLS * C_DIM];    // 10 KB
    __shared__ float b2[N_CLS];
    __shared__ float ts[128][C_DIM + 1];   // 33 KB, conflict-free column walk

    const int tid = threadIdx.x;           // 128 threads
    for (int i = tid; i < N_CLS * C_DIM; i += 128) w2[i] = Wp2[i];
    if (tid < N_CLS) b2[tid] = bp2[tid];

    const int nodeBase = blockIdx.x * 128;
    for (int i = tid; i < 128 * C_DIM; i += 128) {
        int r = i / C_DIM, c = i % C_DIM;
        int node = nodeBase + r;
        ts[r][c] = (node < N_NODES) ? g_t[(size_t)node * C_DIM + c] : 0.f;
    }
    __syncthreads();

    const int node = nodeBase + tid;
    if (node >= N_NODES) return;

    float logits[N_CLS];
    #pragma unroll
    for (int j = 0; j < N_CLS; j++) logits[j] = b2[j];
    #pragma unroll 4
    for (int k = 0; k < C_DIM; k++) {
        float tv = ts[tid][k];
        #pragma unroll
        for (int j = 0; j < N_CLS; j++) logits[j] += tv * w2[j * C_DIM + k];
    }

    float m = logits[0];
    #pragma unroll
    for (int j = 1; j < N_CLS; j++) m = fmaxf(m, logits[j]);
    float se = 0.f;
    #pragma unroll
    for (int j = 0; j < N_CLS; j++) se += __expf(logits[j] - m);
    float lse = m + __logf(se);
    #pragma unroll
    for (int j = 0; j < N_CLS; j++)
        out[(size_t)node * N_CLS + j] = logits[j] - lse;
}

// ---------------- launch ----------------
extern "C" void kernel_launch(void* const* d_in, const int* in_sizes, int n_in,
                              void* d_out, int out_size) {
    const float* x   = (const float*)d_in[0];
    const int*   ei  = (const int*)  d_in[1];
    const float* W0  = (const float*)d_in[2];
    const float* b0  = (const float*)d_in[3];
    const float* al0 = (const float*)d_in[4];
    const float* W1  = (const float*)d_in[6];
    const float* b1  = (const float*)d_in[7];
    const float* al1 = (const float*)d_in[8];
    const float* W2  = (const float*)d_in[10];
    const float* b2  = (const float*)d_in[11];
    const float* al2 = (const float*)d_in[12];
    const float* Wp1 = (const float*)d_in[14];
    const float* bp1 = (const float*)d_in[15];
    const float* Wp2 = (const float*)d_in[16];
    const float* bp2 = (const float*)d_in[17];
    float* out = (float*)d_out;

    const int* srcv = ei;
    const int* dstv = ei + N_EDGES;

    float *h0, *h1, *tb;
    cudaGetSymbolAddress((void**)&h0, g_h0);
    cudaGetSymbolAddress((void**)&h1, g_h1);
    cudaGetSymbolAddress((void**)&tb, g_t);

    // CSR by destination
    zero_deg_kernel<<<(N_NODES + 255) / 256, 256>>>();
    count_deg_kernel<<<(N_EDGES + 255) / 256, 256>>>(dstv);
    scan_kernel<<<1, 1024>>>();
    scatter_kernel<<<(N_EDGES + 255) / 256, 256>>>(srcv, dstv);

    const int gemmGrid = (N_NODES + 127) / 128;
    const int aggGrid  = (N_NODES + 7) / 8;

    // layer 0
    sgemm_bias<128, 8><<<gemmGrid, 256>>>(x,  W0, b0, h0);
    gat_agg<<<aggGrid, 256>>>(h0, al0, h1);
    // layer 1
    sgemm_bias<128, 8><<<gemmGrid, 256>>>(h1, W1, b1, h0);
    gat_agg<<<aggGrid, 256>>>(h0, al1, h1);
    // layer 2
    sgemm_bias<128, 8><<<gemmGrid, 256>>>(h1, W2, b2, h0);
    gat_agg<<<aggGrid, 256>>>(h0, al2, h1);
    // head
    sgemm_bias<64, 4><<<gemmGrid, 256>>>(h1, Wp1, bp1, tb);
    proj2_kernel<<<(N_NODES + 127) / 128, 128>>>(Wp2, bp2, out);
}

// round 3
// speedup vs baseline: 1.0003x; 1.0003x over previous
#include <cuda_runtime.h>
#include <cuda_bf16.h>
#include <math.h>
#include <cstdint>

#define N_NODES 100000
#define N_EDGES 800000
#define HCDIM   128
#define C_DIM   64
#define N_CLS   40
#define EPS_F   1e-16f

// ---------------- static device scratch ----------------
__device__ __align__(16) float g_h0[(size_t)N_NODES * HCDIM];
__device__ __align__(16) float g_h1[(size_t)N_NODES * HCDIM];
__device__ __align__(16) float g_t [(size_t)N_NODES * C_DIM];
__device__ int g_deg[N_NODES];
__device__ int g_rowptr[N_NODES + 1];
__device__ int g_cursor[N_NODES];
__device__ int g_csrc[N_EDGES];
__device__ unsigned g_cmax_u[HCDIM];

// ---------------- helpers ----------------
__device__ __forceinline__ uint32_t smem_to_u32(const void* p) {
    uint32_t a;
    asm("{ .reg .u64 t; cvta.to.shared.u64 t, %1; cvt.u32.u64 %0, t; }" : "=r"(a) : "l"(p));
    return a;
}

__device__ __forceinline__ void ldmatrix_x4(uint32_t* r, uint32_t addr) {
    asm volatile("ldmatrix.sync.aligned.m8n8.x4.shared.b16 {%0,%1,%2,%3}, [%4];"
        : "=r"(r[0]), "=r"(r[1]), "=r"(r[2]), "=r"(r[3]) : "r"(addr));
}
__device__ __forceinline__ void ldmatrix_x2(uint32_t* r, uint32_t addr) {
    asm volatile("ldmatrix.sync.aligned.m8n8.x2.shared.b16 {%0,%1}, [%2];"
        : "=r"(r[0]), "=r"(r[1]) : "r"(addr));
}
__device__ __forceinline__ void mma_bf16(float* c, const uint32_t* a, const uint32_t* b) {
    asm volatile("mma.sync.aligned.m16n8k16.row.col.f32.bf16.bf16.f32 "
        "{%0,%1,%2,%3}, {%4,%5,%6,%7}, {%8,%9}, {%0,%1,%2,%3};"
        : "+f"(c[0]), "+f"(c[1]), "+f"(c[2]), "+f"(c[3])
        : "r"(a[0]), "r"(a[1]), "r"(a[2]), "r"(a[3]), "r"(b[0]), "r"(b[1]));
}

__device__ __forceinline__ uint32_t pack_bf16(float a, float b) {
    __nv_bfloat162 p = __floats2bfloat162_rn(a, b);
    return *reinterpret_cast<uint32_t*>(&p);
}

// ---------------- CSR build ----------------
__global__ void zero_deg_kernel() {
    int i = blockIdx.x * blockDim.x + threadIdx.x;
    if (i < N_NODES) g_deg[i] = 0;
}

__global__ void count_deg_kernel(const int* __restrict__ dst) {
    int e = blockIdx.x * blockDim.x + threadIdx.x;
    if (e < N_EDGES) atomicAdd(&g_deg[dst[e]], 1);
}

__global__ void scan_kernel() {
    __shared__ int warp_sums[32];
    __shared__ int sCarry;
    const int tid  = threadIdx.x;       // 1024
    const int lane = tid & 31;
    const int wid  = tid >> 5;
    if (tid == 0) sCarry = 0;
    __syncthreads();
    for (int base = 0; base < N_NODES; base += 1024) {
        int idx = base + tid;
        int v = (idx < N_NODES) ? g_deg[idx] : 0;
        int incl = v;
        #pragma unroll
        for (int d = 1; d < 32; d <<= 1) {
            int t = __shfl_up_sync(0xffffffffu, incl, d);
            if (lane >= d) incl += t;
        }
        if (lane == 31) warp_sums[wid] = incl;
        __syncthreads();
        if (wid == 0) {
            int s = warp_sums[lane];
            #pragma unroll
            for (int d = 1; d < 32; d <<= 1) {
                int t = __shfl_up_sync(0xffffffffu, s, d);
                if (lane >= d) s += t;
            }
            warp_sums[lane] = s;
        }
        __syncthreads();
        int carry = sCarry;
        int woff  = (wid > 0) ? warp_sums[wid - 1] : 0;
        int excl  = carry + woff + incl - v;
        if (idx < N_NODES) { g_rowptr[idx] = excl; g_cursor[idx] = excl; }
        __syncthreads();
        if (tid == 0) sCarry = carry + warp_sums[31];
        __syncthreads();
    }
    if (tid == 0) g_rowptr[N_NODES] = N_EDGES;
}

__global__ void scatter_kernel(const int* __restrict__ src, const int* __restrict__ dst) {
    int e = blockIdx.x * blockDim.x + threadIdx.x;
    if (e < N_EDGES) {
        int d   = dst[e];
        int pos = atomicAdd(&g_cursor[d], 1);
        g_csrc[pos] = src[e];
    }
}

// ---------------- HMMA split-bf16 GEMM: Out[N,BN] = A[N,128] @ W[BN,128]^T + b ----------
// Per block: 128 rows x BN cols, 8 warps, warp w owns rows [16w, 16w+16).
// A,W split to bf16 hi+lo in smem; acc += Ah*Bh + Ah*Bl + Al*Bh (fp32 accum).

template <int BN>
__global__ void __launch_bounds__(256, 1) hmma_gemm(
    const float* __restrict__ A, const float* __restrict__ W,
    const float* __restrict__ bias, float* __restrict__ Out)
{
    constexpr int LD = 136;               // bf16 elems per row (272B: 4-bank shift/row)
    constexpr int NT = BN / 8;
    extern __shared__ char smem[];
    const uint32_t su = smem_to_u32(smem);
    const uint32_t OFF_AH = 0;
    const uint32_t OFF_AL = 128 * LD * 2;
    const uint32_t OFF_BH = OFF_AL + 128 * LD * 2;
    const uint32_t OFF_BL = OFF_BH + BN * LD * 2;

    const int tid  = threadIdx.x;
    const int warp = tid >> 5;
    const int lane = tid & 31;
    const int rowBase = blockIdx.x * 128;

    // ---- convert A rows (fp32 -> bf16 hi/lo) ----
    for (int i = tid; i < 128 * 32; i += 256) {      // 32 float4 per row
        int r = i >> 5, c = (i & 31) * 4;
        int grow = rowBase + r;
        float4 v = make_float4(0.f, 0.f, 0.f, 0.f);
        if (grow < N_NODES) v = *(const float4*)(A + (size_t)grow * 128 + c);
        float hx = __bfloat162float(__float2bfloat16_rn(v.x));
        float hy = __bfloat162float(__float2bfloat16_rn(v.y));
        float hz = __bfloat162float(__float2bfloat16_rn(v.z));
        float hw = __bfloat162float(__float2bfloat16_rn(v.w));
        uint2 hi = make_uint2(pack_bf16(v.x, v.y), pack_bf16(v.z, v.w));
        uint2 lo = make_uint2(pack_bf16(v.x - hx, v.y - hy), pack_bf16(v.z - hz, v.w - hw));
        *(uint2*)(smem + OFF_AH + ((size_t)r * LD + c) * 2) = hi;
        *(uint2*)(smem + OFF_AL + ((size_t)r * LD + c) * 2) = lo;
    }
    // ---- convert W rows ----
    for (int i = tid; i < BN * 32; i += 256) {
        int r = i >> 5, c = (i & 31) * 4;
        float4 v = *(const float4*)(W + (size_t)r * 128 + c);
        float hx = __bfloat162float(__float2bfloat16_rn(v.x));
        float hy = __bfloat162float(__float2bfloat16_rn(v.y));
        float hz = __bfloat162float(__float2bfloat16_rn(v.z));
        float hw = __bfloat162float(__float2bfloat16_rn(v.w));
        uint2 hi = make_uint2(pack_bf16(v.x, v.y), pack_bf16(v.z, v.w));
        uint2 lo = make_uint2(pack_bf16(v.x - hx, v.y - hy), pack_bf16(v.z - hz, v.w - hw));
        *(uint2*)(smem + OFF_BH + ((size_t)r * LD + c) * 2) = hi;
        *(uint2*)(smem + OFF_BL + ((size_t)r * LD + c) * 2) = lo;
    }
    __syncthreads();

    // ---- mma mainloop ----
    float acc[NT][4];
    #pragma unroll
    for (int n = 0; n < NT; n++)
        #pragma unroll
        for (int j = 0; j < 4; j++) acc[n][j] = 0.f;

    // A fragment lane address (bytes): row = 16*warp + (lane&7) + ((lane>>3)&1)*8, col = (lane>>4)*8
    const uint32_t a_lane_off =
        (uint32_t)(((warp * 16 + (lane & 7) + ((lane >> 3) & 1) * 8) * LD + ((lane >> 4) * 8)) * 2);
    // B fragment lane address: row(n) = (lane&7), col = ((lane>>3)&1)*8
    const uint32_t b_lane_off =
        (uint32_t)(((lane & 7) * LD + ((lane >> 3) & 1) * 8) * 2);

    #pragma unroll
    for (int k0 = 0; k0 < 128; k0 += 16) {
        uint32_t ah[4], al[4];
        ldmatrix_x4(ah, su + OFF_AH + a_lane_off + k0 * 2);
        ldmatrix_x4(al, su + OFF_AL + a_lane_off + k0 * 2);
        #pragma unroll
        for (int n = 0; n < NT; n++) {
            uint32_t bh[2], bl[2];
            uint32_t boff = b_lane_off + (uint32_t)(n * 8 * LD * 2) + k0 * 2;
            ldmatrix_x2(bh, su + OFF_BH + boff);
            ldmatrix_x2(bl, su + OFF_BL + boff);
            mma_bf16(acc[n], ah, bh);
            mma_bf16(acc[n], ah, bl);
            mma_bf16(acc[n], al, bh);
        }
    }

    // ---- epilogue ----
    const int r0 = rowBase + warp * 16 + (lane >> 2);
    const int r1 = r0 + 8;
    #pragma unroll
    for (int n = 0; n < NT; n++) {
        const int col = n * 8 + (lane & 3) * 2;
        const float bx = bias[col], by = bias[col + 1];
        if (r0 < N_NODES) {
            float2 o0 = make_float2(acc[n][0] + bx, acc[n][1] + by);
            *(float2*)(Out + (size_t)r0 * BN + col) = o0;
        }
        if (r1 < N_NODES) {
            float2 o1 = make_float2(acc[n][2] + bx, acc[n][3] + by);
            *(float2*)(Out + (size_t)r1 * BN + col) = o1;
        }
    }
}

// ---------------- per-channel global max of al_c * h[v,c] ----------------
__global__ void init_cmax_kernel() {
    g_cmax_u[threadIdx.x] = 0x007FFFFFu;   // encode(-inf)
}

__global__ void colmax_kernel(const float* __restrict__ h, const float* __restrict__ al) {
    const int c = threadIdx.x;             // 128 threads
    const float a = al[c];
    const int r0 = blockIdx.x * 256;
    const int r1 = min(N_NODES, r0 + 256);
    float m = -INFINITY;
    for (int r = r0; r < r1; r++)
        m = fmaxf(m, a * h[(size_t)r * HCDIM + c]);
    unsigned bits = __float_as_uint(m);
    unsigned enc = (bits & 0x80000000u) ? ~bits : (bits | 0x80000000u);
    atomicMax(&g_cmax_u[c], enc);
}

__device__ __forceinline__ float dec_max(unsigned u) {
    return (u & 0x80000000u) ? __uint_as_float(u ^ 0x80000000u) : __uint_as_float(~u);
}

// ---------------- GAT aggregation: warp per dst node, single pass ----------------
__global__ void gat_agg(const float* __restrict__ h, const float* __restrict__ al,
                        float* __restrict__ out) {
    const int warpsPerBlock = blockDim.x >> 5;
    const int node = blockIdx.x * warpsPerBlock + (threadIdx.x >> 5);
    if (node >= N_NODES) return;
    const int lane = threadIdx.x & 31;

    const float4 a4 = *(const float4*)(al + lane * 4);
    float4 m4;
    {
        uint4 u = *(const uint4*)(g_cmax_u + lane * 4);
        m4.x = dec_max(u.x); m4.y = dec_max(u.y);
        m4.z = dec_max(u.z); m4.w = dec_max(u.w);
    }
    const int beg = g_rowptr[node];
    const int end = g_rowptr[node + 1];

    float4 S   = make_float4(0.f, 0.f, 0.f, 0.f);
    float4 acc = make_float4(0.f, 0.f, 0.f, 0.f);
    for (int base = beg; base < end; base += 32) {
        int cnt = min(32, end - base);
        int s = (lane < cnt) ? g_csrc[base + lane] : 0;
        for (int i = 0; i < cnt; i++) {
            int src = __shfl_sync(0xffffffffu, s, i);
            float4 v = *(const float4*)(h + (size_t)src * HCDIM + lane * 4);
            float wx = __expf(a4.x * v.x - m4.x);
            float wy = __expf(a4.y * v.y - m4.y);
            float wz = __expf(a4.z * v.z - m4.z);
            float ww = __expf(a4.w * v.w - m4.w);
            S.x += wx; S.y += wy; S.z += wz; S.w += ww;
            acc.x += wx * v.x; acc.y += wy * v.y;
            acc.z += wz * v.z; acc.w += ww * v.w;
        }
    }

    float4 o;
    o.x = fmaxf(acc.x / (S.x + EPS_F), 0.f);
    o.y = fmaxf(acc.y / (S.y + EPS_F), 0.f);
    o.z = fmaxf(acc.z / (S.z + EPS_F), 0.f);
    o.w = fmaxf(acc.w / (S.w + EPS_F), 0.f);
    *(float4*)(out + (size_t)node * HCDIM + lane * 4) = o;
}

// ---------------- head: logits + log_softmax ----------------
__global__ void proj2_kernel(const float* __restrict__ Wp2, const float* __restrict__ bp2,
                             float* __restrict__ out) {
    __shared__ float w2[N_CLS * C_DIM];
    __shared__ float b2[N_CLS];
    __shared__ float ts[128][C_DIM + 1];

    const int tid = threadIdx.x;           // 128
    for (int i = tid; i < N_CLS * C_DIM; i += 128) w2[i] = Wp2[i];
    if (tid < N_CLS) b2[tid] = bp2[tid];

    const int nodeBase = blockIdx.x * 128;
    for (int i = tid; i < 128 * C_DIM; i += 128) {
        int r = i / C_DIM, c = i % C_DIM;
        int node = nodeBase + r;
        ts[r][c] = (node < N_NODES) ? g_t[(size_t)node * C_DIM + c] : 0.f;
    }
    __syncthreads();

    const int node = nodeBase + tid;
    if (node >= N_NODES) return;

    float logits[N_CLS];
    #pragma unroll
    for (int j = 0; j < N_CLS; j++) logits[j] = b2[j];
    #pragma unroll 4
    for (int k = 0; k < C_DIM; k++) {
        float tv = ts[tid][k];
        #pragma unroll
        for (int j = 0; j < N_CLS; j++) logits[j] += tv * w2[j * C_DIM + k];
    }

    float m = logits[0];
    #pragma unroll
    for (int j = 1; j < N_CLS; j++) m = fmaxf(m, logits[j]);
    float se = 0.f;
    #pragma unroll
    for (int j = 0; j < N_CLS; j++) se += __expf(logits[j] - m);
    float lse = m + __logf(se);
    #pragma unroll
    for (int j = 0; j < N_CLS; j++)
        out[(size_t)node * N_CLS + j] = logits[j] - lse;
}

// ---------------- launch ----------------
extern "C" void kernel_launch(void* const* d_in, const int* in_sizes, int n_in,
                              void* d_out, int out_size) {
    const float* x   = (const float*)d_in[0];
    const int*   ei  = (const int*)  d_in[1];
    const float* W0  = (const float*)d_in[2];
    const float* b0  = (const float*)d_in[3];
    const float* al0 = (const float*)d_in[4];
    const float* W1  = (const float*)d_in[6];
    const float* b1  = (const float*)d_in[7];
    const float* al1 = (const float*)d_in[8];
    const float* W2  = (const float*)d_in[10];
    const float* b2  = (const float*)d_in[11];
    const float* al2 = (const float*)d_in[12];
    const float* Wp1 = (const float*)d_in[14];
    const float* bp1 = (const float*)d_in[15];
    const float* Wp2 = (const float*)d_in[16];
    const float* bp2 = (const float*)d_in[17];
    float* out = (float*)d_out;

    const int* srcv = ei;
    const int* dstv = ei + N_EDGES;

    float *h0, *h1, *tb;
    cudaGetSymbolAddress((void**)&h0, g_h0);
    cudaGetSymbolAddress((void**)&h1, g_h1);
    cudaGetSymbolAddress((void**)&tb, g_t);

    constexpr int LD = 136;
    const int SMEM128 = (2 * 128 * LD + 2 * 128 * LD) * 2;  // 139264
    const int SMEM64  = (2 * 128 * LD + 2 * 64  * LD) * 2;  // 104448
    static bool attr_done = false;
    if (!attr_done) {
        cudaFuncSetAttribute(hmma_gemm<128>, cudaFuncAttributeMaxDynamicSharedMemorySize, SMEM128);
        cudaFuncSetAttribute(hmma_gemm<64>,  cudaFuncAttributeMaxDynamicSharedMemorySize, SMEM64);
        attr_done = true;
    }

    // CSR by destination
    zero_deg_kernel<<<(N_NODES + 255) / 256, 256>>>();
    count_deg_kernel<<<(N_EDGES + 255) / 256, 256>>>(dstv);
    scan_kernel<<<1, 1024>>>();
    scatter_kernel<<<(N_EDGES + 255) / 256, 256>>>(srcv, dstv);

    const int gemmGrid = (N_NODES + 127) / 128;   // 782
    const int aggGrid  = (N_NODES + 7) / 8;
    const int cmGrid   = (N_NODES + 255) / 256;

    // layer 0
    hmma_gemm<128><<<gemmGrid, 256, SMEM128>>>(x, W0, b0, h0);
    init_cmax_kernel<<<1, 128>>>();
    colmax_kernel<<<cmGrid, 128>>>(h0, al0);
    gat_agg<<<aggGrid, 256>>>(h0, al0, h1);
    // layer 1
    hmma_gemm<128><<<gemmGrid, 256, SMEM128>>>(h1, W1, b1, h0);
    init_cmax_kernel<<<1, 128>>>();
    colmax_kernel<<<cmGrid, 128>>>(h0, al1);
    gat_agg<<<aggGrid, 256>>>(h0, al1, h1);
    // layer 2
    hmma_gemm<128><<<gemmGrid, 256, SMEM128>>>(h1, W2, b2, h0);
    init_cmax_kernel<<<1, 128>>>();
    colmax_kernel<<<cmGrid, 128>>>(h0, al2);
    gat_agg<<<aggGrid, 256>>>(h0, al2, h1);
    // head
    hmma_gemm<64><<<gemmGrid, 256, SMEM64>>>(h1, Wp1, bp1, tb);
    proj2_kernel<<<(N_NODES + 127) / 128, 128>>>(Wp2, bp2, out);
}

// round 4
// speedup vs baseline: 1.1528x; 1.1525x over previous
#include <cuda_runtime.h>
#include <cuda_bf16.h>
#include <cuda_fp16.h>
#include <math.h>
#include <cstdint>

#define N_NODES 100000
#define N_EDGES 800000
#define HCDIM   128
#define C_DIM   64
#define N_CLS   40
#define EPS_F   1e-16f

// ---------------- static device scratch ----------------
__device__ __align__(16) float   g_hin[(size_t)N_NODES * HCDIM];  // agg output / gemm input
__device__ __align__(16) __half2 g_pq [(size_t)N_NODES * HCDIM];  // (P,Q) per channel
__device__ __align__(16) float   g_t  [(size_t)N_NODES * C_DIM];
__device__ int g_deg[N_NODES];
__device__ int g_rowptr[N_NODES + 1];
__device__ int g_cursor[N_NODES];
__device__ int g_csrc[N_EDGES];

// ---------------- helpers ----------------
__device__ __forceinline__ uint32_t smem_to_u32(const void* p) {
    uint32_t a;
    asm("{ .reg .u64 t; cvta.to.shared.u64 t, %1; cvt.u32.u64 %0, t; }" : "=r"(a) : "l"(p));
    return a;
}
__device__ __forceinline__ void ldmatrix_x4(uint32_t* r, uint32_t addr) {
    asm volatile("ldmatrix.sync.aligned.m8n8.x4.shared.b16 {%0,%1,%2,%3}, [%4];"
        : "=r"(r[0]), "=r"(r[1]), "=r"(r[2]), "=r"(r[3]) : "r"(addr));
}
__device__ __forceinline__ void ldmatrix_x2(uint32_t* r, uint32_t addr) {
    asm volatile("ldmatrix.sync.aligned.m8n8.x2.shared.b16 {%0,%1}, [%2];"
        : "=r"(r[0]), "=r"(r[1]) : "r"(addr));
}
__device__ __forceinline__ void mma_bf16(float* c, const uint32_t* a, const uint32_t* b) {
    asm volatile("mma.sync.aligned.m16n8k16.row.col.f32.bf16.bf16.f32 "
        "{%0,%1,%2,%3}, {%4,%5,%6,%7}, {%8,%9}, {%0,%1,%2,%3};"
        : "+f"(c[0]), "+f"(c[1]), "+f"(c[2]), "+f"(c[3])
        : "r"(a[0]), "r"(a[1]), "r"(a[2]), "r"(a[3]), "r"(b[0]), "r"(b[1]));
}
__device__ __forceinline__ uint32_t pack_bf16(float a, float b) {
    __nv_bfloat162 p = __floats2bfloat162_rn(a, b);
    return *reinterpret_cast<uint32_t*>(&p);
}

// ---------------- CSR build (3 launches) ----------------
__global__ void count_deg_kernel(const int* __restrict__ dst) {
    int e = blockIdx.x * blockDim.x + threadIdx.x;
    if (e < N_EDGES) atomicAdd(&g_deg[dst[e]], 1);
}

// single-block chunked exclusive scan; also re-zeroes g_deg for the next replay
__global__ void scan_kernel() {
    __shared__ int warp_sums[32];
    __shared__ int sCarry;
    const int tid  = threadIdx.x;       // 1024
    const int lane = tid & 31;
    const int wid  = tid >> 5;
    if (tid == 0) sCarry = 0;
    __syncthreads();
    for (int base = 0; base < N_NODES; base += 1024) {
        int idx = base + tid;
        int v = (idx < N_NODES) ? g_deg[idx] : 0;
        if (idx < N_NODES) g_deg[idx] = 0;          // reset for next graph replay
        int incl = v;
        #pragma unroll
        for (int d = 1; d < 32; d <<= 1) {
            int t = __shfl_up_sync(0xffffffffu, incl, d);
            if (lane >= d) incl += t;
        }
        if (lane == 31) warp_sums[wid] = incl;
        __syncthreads();
        if (wid == 0) {
            int s = warp_sums[lane];
            #pragma unroll
            for (int d = 1; d < 32; d <<= 1) {
                int t = __shfl_up_sync(0xffffffffu, s, d);
                if (lane >= d) s += t;
            }
            warp_sums[lane] = s;
        }
        __syncthreads();
        int carry = sCarry;
        int woff  = (wid > 0) ? warp_sums[wid - 1] : 0;
        int excl  = carry + woff + incl - v;
        if (idx < N_NODES) { g_rowptr[idx] = excl; g_cursor[idx] = excl; }
        __syncthreads();
        if (tid == 0) sCarry = carry + warp_sums[31];
        __syncthreads();
    }
    if (tid == 0) g_rowptr[N_NODES] = N_EDGES;
}

__global__ void scatter_kernel(const int* __restrict__ src, const int* __restrict__ dst) {
    int e = blockIdx.x * blockDim.x + threadIdx.x;
    if (e < N_EDGES) {
        int d   = dst[e];
        int pos = atomicAdd(&g_cursor[d], 1);
        g_csrc[pos] = src[e];
    }
}

// ---------------- HMMA split-bf16 GEMM ----------------
// Out = A[N,128] @ W[BN,128]^T + b. 128 rows/block, 8 warps.
// PQ_MODE: instead of writing h, write half2(P,Q) = (exp(al*h), exp(al*h)*h).

template <int BN, bool PQ_MODE>
__global__ void __launch_bounds__(256, 1) hmma_gemm(
    const float* __restrict__ A, const float* __restrict__ W,
    const float* __restrict__ bias, const float* __restrict__ al,
    float* __restrict__ Out)
{
    constexpr int LD = 136;
    constexpr int NT = BN / 8;
    extern __shared__ char smem[];
    const uint32_t su = smem_to_u32(smem);
    const uint32_t OFF_AH = 0;
    const uint32_t OFF_AL = 128 * LD * 2;
    const uint32_t OFF_BH = OFF_AL + 128 * LD * 2;
    const uint32_t OFF_BL = OFF_BH + BN * LD * 2;

    const int tid  = threadIdx.x;
    const int warp = tid >> 5;
    const int lane = tid & 31;
    const int rowBase = blockIdx.x * 128;

    for (int i = tid; i < 128 * 32; i += 256) {
        int r = i >> 5, c = (i & 31) * 4;
        int grow = rowBase + r;
        float4 v = make_float4(0.f, 0.f, 0.f, 0.f);
        if (grow < N_NODES) v = *(const float4*)(A + (size_t)grow * 128 + c);
        float hx = __bfloat162float(__float2bfloat16_rn(v.x));
        float hy = __bfloat162float(__float2bfloat16_rn(v.y));
        float hz = __bfloat162float(__float2bfloat16_rn(v.z));
        float hw = __bfloat162float(__float2bfloat16_rn(v.w));
        uint2 hi = make_uint2(pack_bf16(v.x, v.y), pack_bf16(v.z, v.w));
        uint2 lo = make_uint2(pack_bf16(v.x - hx, v.y - hy), pack_bf16(v.z - hz, v.w - hw));
        *(uint2*)(smem + OFF_AH + ((size_t)r * LD + c) * 2) = hi;
        *(uint2*)(smem + OFF_AL + ((size_t)r * LD + c) * 2) = lo;
    }
    for (int i = tid; i < BN * 32; i += 256) {
        int r = i >> 5, c = (i & 31) * 4;
        float4 v = *(const float4*)(W + (size_t)r * 128 + c);
        float hx = __bfloat162float(__float2bfloat16_rn(v.x));
        float hy = __bfloat162float(__float2bfloat16_rn(v.y));
        float hz = __bfloat162float(__float2bfloat16_rn(v.z));
        float hw = __bfloat162float(__float2bfloat16_rn(v.w));
        uint2 hi = make_uint2(pack_bf16(v.x, v.y), pack_bf16(v.z, v.w));
        uint2 lo = make_uint2(pack_bf16(v.x - hx, v.y - hy), pack_bf16(v.z - hz, v.w - hw));
        *(uint2*)(smem + OFF_BH + ((size_t)r * LD + c) * 2) = hi;
        *(uint2*)(smem + OFF_BL + ((size_t)r * LD + c) * 2) = lo;
    }
    __syncthreads();

    float acc[NT][4];
    #pragma unroll
    for (int n = 0; n < NT; n++)
        #pragma unroll
        for (int j = 0; j < 4; j++) acc[n][j] = 0.f;

    const uint32_t a_lane_off =
        (uint32_t)(((warp * 16 + (lane & 7) + ((lane >> 3) & 1) * 8) * LD + ((lane >> 4) * 8)) * 2);
    const uint32_t b_lane_off =
        (uint32_t)(((lane & 7) * LD + ((lane >> 3) & 1) * 8) * 2);

    #pragma unroll
    for (int k0 = 0; k0 < 128; k0 += 16) {
        uint32_t ah[4], alr[4];
        ldmatrix_x4(ah,  su + OFF_AH + a_lane_off + k0 * 2);
        ldmatrix_x4(alr, su + OFF_AL + a_lane_off + k0 * 2);
        #pragma unroll
        for (int n = 0; n < NT; n++) {
            uint32_t bh[2], bl[2];
            uint32_t boff = b_lane_off + (uint32_t)(n * 8 * LD * 2) + k0 * 2;
            ldmatrix_x2(bh, su + OFF_BH + boff);
            ldmatrix_x2(bl, su + OFF_BL + boff);
            mma_bf16(acc[n], ah, bh);
            mma_bf16(acc[n], ah, bl);
            mma_bf16(acc[n], alr, bh);
        }
    }

    const int r0 = rowBase + warp * 16 + (lane >> 2);
    const int r1 = r0 + 8;
    #pragma unroll
    for (int n = 0; n < NT; n++) {
        const int col = n * 8 + (lane & 3) * 2;
        const float bx = bias[col], by = bias[col + 1];
        if (PQ_MODE) {
            const float a0 = al[col], a1 = al[col + 1];
            if (r0 < N_NODES) {
                float h0v = acc[n][0] + bx, h1v = acc[n][1] + by;
                float P0 = __expf(a0 * h0v), P1 = __expf(a1 * h1v);
                __half2 x0 = __floats2half2_rn(P0, P0 * h0v);
                __half2 x1 = __floats2half2_rn(P1, P1 * h1v);
                uint2 u; u.x = *(uint32_t*)&x0; u.y = *(uint32_t*)&x1;
                *(uint2*)(g_pq + (size_t)r0 * 128 + col) = u;
            }
            if (r1 < N_NODES) {
                float h0v = acc[n][2] + bx, h1v = acc[n][3] + by;
                float P0 = __expf(a0 * h0v), P1 = __expf(a1 * h1v);
                __half2 x0 = __floats2half2_rn(P0, P0 * h0v);
                __half2 x1 = __floats2half2_rn(P1, P1 * h1v);
                uint2 u; u.x = *(uint32_t*)&x0; u.y = *(uint32_t*)&x1;
                *(uint2*)(g_pq + (size_t)r1 * 128 + col) = u;
            }
        } else {
            if (r0 < N_NODES)
                *(float2*)(Out + (size_t)r0 * BN + col) = make_float2(acc[n][0] + bx, acc[n][1] + by);
            if (r1 < N_NODES)
                *(float2*)(Out + (size_t)r1 * BN + col) = make_float2(acc[n][2] + bx, acc[n][3] + by);
        }
    }
}

// ---------------- aggregation: warp/node, pure gather-add over (P,Q) ----------------
__global__ void gat_agg_sum(float* __restrict__ out) {
    const int node = blockIdx.x * (blockDim.x >> 5) + (threadIdx.x >> 5);
    if (node >= N_NODES) return;
    const int lane = threadIdx.x & 31;
    const int beg = g_rowptr[node];
    const int end = g_rowptr[node + 1];

    float S0=0.f,S1=0.f,S2=0.f,S3=0.f;
    float A0=0.f,A1=0.f,A2=0.f,A3=0.f;

    const uint4* __restrict__ pq = (const uint4*)g_pq;   // row = 32 uint4
    #define ACCUM(v) do { \
        __half2 p0 = *(__half2*)&(v).x, p1 = *(__half2*)&(v).y; \
        __half2 p2 = *(__half2*)&(v).z, p3 = *(__half2*)&(v).w; \
        float2 f0 = __half22float2(p0), f1 = __half22float2(p1); \
        float2 f2 = __half22float2(p2), f3 = __half22float2(p3); \
        S0 += f0.x; A0 += f0.y;  S1 += f1.x; A1 += f1.y; \
        S2 += f2.x; A2 += f2.y;  S3 += f3.x; A3 += f3.y; \
    } while (0)

    int e = beg;
    for (; e + 4 <= end; e += 4) {
        int s0 = __ldg(&g_csrc[e + 0]);
        int s1 = __ldg(&g_csrc[e + 1]);
        int s2 = __ldg(&g_csrc[e + 2]);
        int s3 = __ldg(&g_csrc[e + 3]);
        uint4 v0 = pq[(size_t)s0 * 32 + lane];
        uint4 v1 = pq[(size_t)s1 * 32 + lane];
        uint4 v2 = pq[(size_t)s2 * 32 + lane];
        uint4 v3 = pq[(size_t)s3 * 32 + lane];
        ACCUM(v0); ACCUM(v1); ACCUM(v2); ACCUM(v3);
    }
    for (; e < end; e++) {
        int s = __ldg(&g_csrc[e]);
        uint4 v = pq[(size_t)s * 32 + lane];
        ACCUM(v);
    }
    #undef ACCUM

    float4 o;
    o.x = fmaxf(A0 / (S0 + EPS_F), 0.f);
    o.y = fmaxf(A1 / (S1 + EPS_F), 0.f);
    o.z = fmaxf(A2 / (S2 + EPS_F), 0.f);
    o.w = fmaxf(A3 / (S3 + EPS_F), 0.f);
    *(float4*)(out + (size_t)node * HCDIM + lane * 4) = o;
}

// ---------------- head: logits + log_softmax ----------------
__global__ void proj2_kernel(const float* __restrict__ Wp2, const float* __restrict__ bp2,
                             float* __restrict__ out) {
    __shared__ float w2[N_CLS * C_DIM];
    __shared__ float b2[N_CLS];
    __shared__ float ts[128][C_DIM + 1];

    const int tid = threadIdx.x;           // 128
    for (int i = tid; i < N_CLS * C_DIM; i += 128) w2[i] = Wp2[i];
    if (tid < N_CLS) b2[tid] = bp2[tid];

    const int nodeBase = blockIdx.x * 128;
    for (int i = tid; i < 128 * C_DIM; i += 128) {
        int r = i / C_DIM, c = i % C_DIM;
        int node = nodeBase + r;
        ts[r][c] = (node < N_NODES) ? g_t[(size_t)node * C_DIM + c] : 0.f;
    }
    __syncthreads();

    const int node = nodeBase + tid;
    if (node >= N_NODES) return;

    float logits[N_CLS];
    #pragma unroll
    for (int j = 0; j < N_CLS; j++) logits[j] = b2[j];
    #pragma unroll 4
    for (int k = 0; k < C_DIM; k++) {
        float tv = ts[tid][k];
        #pragma unroll
        for (int j = 0; j < N_CLS; j++) logits[j] += tv * w2[j * C_DIM + k];
    }

    float m = logits[0];
    #pragma unroll
    for (int j = 1; j < N_CLS; j++) m = fmaxf(m, logits[j]);
    float se = 0.f;
    #pragma unroll
    for (int j = 0; j < N_CLS; j++) se += __expf(logits[j] - m);
    float lse = m + __logf(se);
    #pragma unroll
    for (int j = 0; j < N_CLS; j++)
        out[(size_t)node * N_CLS + j] = logits[j] - lse;
}

// ---------------- launch ----------------
extern "C" void kernel_launch(void* const* d_in, const int* in_sizes, int n_in,
                              void* d_out, int out_size) {
    const float* x   = (const float*)d_in[0];
    const int*   ei  = (const int*)  d_in[1];
    const float* W0  = (const float*)d_in[2];
    const float* b0  = (const float*)d_in[3];
    const float* al0 = (const float*)d_in[4];
    const float* W1  = (const float*)d_in[6];
    const float* b1  = (const float*)d_in[7];
    const float* al1 = (const float*)d_in[8];
    const float* W2  = (const float*)d_in[10];
    const float* b2  = (const float*)d_in[11];
    const float* al2 = (const float*)d_in[12];
    const float* Wp1 = (const float*)d_in[14];
    const float* bp1 = (const float*)d_in[15];
    const float* Wp2 = (const float*)d_in[16];
    const float* bp2 = (const float*)d_in[17];
    float* out = (float*)d_out;

    const int* srcv = ei;
    const int* dstv = ei + N_EDGES;

    float *hin, *tb;
    cudaGetSymbolAddress((void**)&hin, g_hin);
    cudaGetSymbolAddress((void**)&tb, g_t);

    constexpr int LD = 136;
    const int SMEM128 = (2 * 128 * LD + 2 * 128 * LD) * 2;
    const int SMEM64  = (2 * 128 * LD + 2 * 64  * LD) * 2;
    static bool attr_done = false;
    if (!attr_done) {
        cudaFuncSetAttribute((const void*)hmma_gemm<128, true>,
                             cudaFuncAttributeMaxDynamicSharedMemorySize, SMEM128);
        cudaFuncSetAttribute((const void*)hmma_gemm<64, false>,
                             cudaFuncAttributeMaxDynamicSharedMemorySize, SMEM64);
        attr_done = true;
    }

    // CSR (3 launches; scan re-zeroes g_deg)
    count_deg_kernel<<<(N_EDGES + 255) / 256, 256>>>(dstv);
    scan_kernel<<<1, 1024>>>();
    scatter_kernel<<<(N_EDGES + 255) / 256, 256>>>(srcv, dstv);

    const int gemmGrid = (N_NODES + 127) / 128;   // 782
    const int aggGrid  = (N_NODES + 7) / 8;

    // layer 0  (launch #4 = hmma_gemm -> ncu target)
    hmma_gemm<128, true><<<gemmGrid, 256, SMEM128>>>(x,   W0, b0, al0, nullptr);
    gat_agg_sum<<<aggGrid, 256>>>(hin);
    // layer 1
    hmma_gemm<128, true><<<gemmGrid, 256, SMEM128>>>(hin, W1, b1, al1, nullptr);
    gat_agg_sum<<<aggGrid, 256>>>(hin);
    // layer 2
    hmma_gemm<128, true><<<gemmGrid, 256, SMEM128>>>(hin, W2, b2, al2, nullptr);
    gat_agg_sum<<<aggGrid, 256>>>(hin);
    // head
    hmma_gemm<64, false><<<gemmGrid, 256, SMEM64>>>(hin, Wp1, bp1, nullptr, tb);
    proj2_kernel<<<(N_NODES + 127) / 128, 128>>>(Wp2, bp2, out);
}

// round 5
// speedup vs baseline: 1.6983x; 1.4732x over previous
#include <cuda_runtime.h>
#include <cuda_bf16.h>
#include <cuda_fp16.h>
#include <math.h>
#include <cstdint>

#define N_NODES 100000
#define N_EDGES 800000
#define HCDIM   128
#define C_DIM   64
#define N_CLS   40
#define EPS_F   1e-16f

// weight scratch layout (bf16 hi/lo): W0[16384] W1[16384] W2[16384] Wp1[8192]
#define WOFF_0  0
#define WOFF_1  16384
#define WOFF_2  32768
#define WOFF_P1 49152
#define WTOT    57344

// ---------------- static device scratch ----------------
__device__ __align__(16) float   g_hin[(size_t)N_NODES * HCDIM];
__device__ __align__(16) __half2 g_pq [(size_t)N_NODES * HCDIM];
__device__ __align__(16) float   g_t  [(size_t)N_NODES * C_DIM];
__device__ __align__(16) __nv_bfloat16 g_wh[WTOT];
__device__ __align__(16) __nv_bfloat16 g_wl[WTOT];
__device__ int g_deg[N_NODES];
__device__ int g_rowptr[N_NODES + 1];
__device__ int g_cursor[N_NODES];
__device__ int g_csrc[N_EDGES];

// ---------------- helpers ----------------
__device__ __forceinline__ uint32_t smem_to_u32(const void* p) {
    uint32_t a;
    asm("{ .reg .u64 t; cvta.to.shared.u64 t, %1; cvt.u32.u64 %0, t; }" : "=r"(a) : "l"(p));
    return a;
}
__device__ __forceinline__ void ldmatrix_x4(uint32_t* r, uint32_t addr) {
    asm volatile("ldmatrix.sync.aligned.m8n8.x4.shared.b16 {%0,%1,%2,%3}, [%4];"
        : "=r"(r[0]), "=r"(r[1]), "=r"(r[2]), "=r"(r[3]) : "r"(addr));
}
__device__ __forceinline__ void ldmatrix_x2(uint32_t* r, uint32_t addr) {
    asm volatile("ldmatrix.sync.aligned.m8n8.x2.shared.b16 {%0,%1}, [%2];"
        : "=r"(r[0]), "=r"(r[1]) : "r"(addr));
}
__device__ __forceinline__ void mma_bf16(float* c, const uint32_t* a, const uint32_t* b) {
    asm volatile("mma.sync.aligned.m16n8k16.row.col.f32.bf16.bf16.f32 "
        "{%0,%1,%2,%3}, {%4,%5,%6,%7}, {%8,%9}, {%0,%1,%2,%3};"
        : "+f"(c[0]), "+f"(c[1]), "+f"(c[2]), "+f"(c[3])
        : "r"(a[0]), "r"(a[1]), "r"(a[2]), "r"(a[3]), "r"(b[0]), "r"(b[1]));
}
__device__ __forceinline__ uint32_t pack_bf16(float a, float b) {
    __nv_bfloat162 p = __floats2bfloat162_rn(a, b);
    return *reinterpret_cast<uint32_t*>(&p);
}

// ---------------- CSR build + weight pre-conversion (fused, 3 launches total) ----------
__global__ void count_deg_convw_kernel(const int* __restrict__ dst,
                                       const float* __restrict__ W0,
                                       const float* __restrict__ W1,
                                       const float* __restrict__ W2,
                                       const float* __restrict__ Wp1) {
    int t = blockIdx.x * blockDim.x + threadIdx.x;
    if (t < N_EDGES) atomicAdd(&g_deg[dst[t]], 1);
    if (t < WTOT) {
        float v;
        if      (t < WOFF_1)  v = W0 [t - WOFF_0];
        else if (t < WOFF_2)  v = W1 [t - WOFF_1];
        else if (t < WOFF_P1) v = W2 [t - WOFF_2];
        else                  v = Wp1[t - WOFF_P1];
        __nv_bfloat16 hi = __float2bfloat16_rn(v);
        g_wh[t] = hi;
        g_wl[t] = __float2bfloat16_rn(v - __bfloat162float(hi));
    }
}

// single-block chunked exclusive scan; re-zeroes g_deg for the next replay
__global__ void scan_kernel() {
    __shared__ int warp_sums[32];
    __shared__ int sCarry;
    const int tid  = threadIdx.x;       // 1024
    const int lane = tid & 31;
    const int wid  = tid >> 5;
    if (tid == 0) sCarry = 0;
    __syncthreads();
    for (int base = 0; base < N_NODES; base += 1024) {
        int idx = base + tid;
        int v = (idx < N_NODES) ? g_deg[idx] : 0;
        if (idx < N_NODES) g_deg[idx] = 0;
        int incl = v;
        #pragma unroll
        for (int d = 1; d < 32; d <<= 1) {
            int t = __shfl_up_sync(0xffffffffu, incl, d);
            if (lane >= d) incl += t;
        }
        if (lane == 31) warp_sums[wid] = incl;
        __syncthreads();
        if (wid == 0) {
            int s = warp_sums[lane];
            #pragma unroll
            for (int d = 1; d < 32; d <<= 1) {
                int t = __shfl_up_sync(0xffffffffu, s, d);
                if (lane >= d) s += t;
            }
            warp_sums[lane] = s;
        }
        __syncthreads();
        int carry = sCarry;
        int woff  = (wid > 0) ? warp_sums[wid - 1] : 0;
        int excl  = carry + woff + incl - v;
        if (idx < N_NODES) { g_rowptr[idx] = excl; g_cursor[idx] = excl; }
        __syncthreads();
        if (tid == 0) sCarry = carry + warp_sums[31];
        __syncthreads();
    }
    if (tid == 0) g_rowptr[N_NODES] = N_EDGES;
}

__global__ void scatter_kernel(const int* __restrict__ src, const int* __restrict__ dst) {
    int e = blockIdx.x * blockDim.x + threadIdx.x;
    if (e < N_EDGES) {
        int d   = dst[e];
        int pos = atomicAdd(&g_cursor[d], 1);
        g_csrc[pos] = src[e];
    }
}

// ---------------- HMMA split-bf16 GEMM, BM=64, high-occupancy ----------------
// Out = A[N,128] @ W[BN,128]^T + b.  8 warps: warp_r=warp&3 (16-row strip),
// warp_c=warp>>2 (BN/2-col half). W comes preconverted (g_wh/g_wl + offset).

template <int BN, bool PQ_MODE>
__global__ void __launch_bounds__(256, 2) hmma_gemm(
    const float* __restrict__ A,
    const __nv_bfloat16* __restrict__ wh, const __nv_bfloat16* __restrict__ wl,
    const float* __restrict__ bias, const float* __restrict__ al,
    float* __restrict__ Out)
{
    constexpr int LD = 136;
    constexpr int NT = BN / 16;           // n8-tiles per warp (half of BN)
    extern __shared__ char smem[];
    const uint32_t su = smem_to_u32(smem);
    const uint32_t OFF_AH = 0;
    const uint32_t OFF_AL = 64 * LD * 2;
    const uint32_t OFF_BH = OFF_AL + 64 * LD * 2;
    const uint32_t OFF_BL = OFF_BH + BN * LD * 2;

    const int tid  = threadIdx.x;
    const int warp = tid >> 5;
    const int lane = tid & 31;
    const int warp_r = warp & 3;
    const int warp_c = warp >> 2;
    const int rowBase = blockIdx.x * 64;

    // ---- stage A (64 rows fp32 -> bf16 hi/lo) ----
    #pragma unroll
    for (int it = 0; it < 8; it++) {
        int i = tid + it * 256;           // 64*32 = 2048 float4 slots
        int r = i >> 5, c = (i & 31) * 4;
        int grow = rowBase + r;
        float4 v = make_float4(0.f, 0.f, 0.f, 0.f);
        if (grow < N_NODES) v = *(const float4*)(A + (size_t)grow * 128 + c);
        float hx = __bfloat162float(__float2bfloat16_rn(v.x));
        float hy = __bfloat162float(__float2bfloat16_rn(v.y));
        float hz = __bfloat162float(__float2bfloat16_rn(v.z));
        float hw = __bfloat162float(__float2bfloat16_rn(v.w));
        uint2 hi = make_uint2(pack_bf16(v.x, v.y), pack_bf16(v.z, v.w));
        uint2 lo = make_uint2(pack_bf16(v.x - hx, v.y - hy), pack_bf16(v.z - hz, v.w - hw));
        *(uint2*)(smem + OFF_AH + ((size_t)r * LD + c) * 2) = hi;
        *(uint2*)(smem + OFF_AL + ((size_t)r * LD + c) * 2) = lo;
    }
    // ---- stage B (preconverted bf16, pure copies) ----
    #pragma unroll
    for (int it = 0; it < BN / 16; it++) {
        int i = tid + it * 256;           // BN*16 uint4 slots
        int r = i >> 4, c = (i & 15) * 8;
        uint4 vh = *(const uint4*)(wh + (size_t)r * 128 + c);
        uint4 vl = *(const uint4*)(wl + (size_t)r * 128 + c);
        *(uint4*)(smem + OFF_BH + ((size_t)r * LD + c) * 2) = vh;
        *(uint4*)(smem + OFF_BL + ((size_t)r * LD + c) * 2) = vl;
    }
    __syncthreads();

    float acc[NT][4];
    #pragma unroll
    for (int n = 0; n < NT; n++)
        #pragma unroll
        for (int j = 0; j < 4; j++) acc[n][j] = 0.f;

    const uint32_t a_lane_off =
        (uint32_t)(((warp_r * 16 + (lane & 7) + ((lane >> 3) & 1) * 8) * LD + ((lane >> 4) * 8)) * 2);
    const uint32_t b_lane_off =
        (uint32_t)(((warp_c * (BN / 2) + (lane & 7)) * LD + ((lane >> 3) & 1) * 8) * 2);

    #pragma unroll
    for (int k0 = 0; k0 < 128; k0 += 16) {
        uint32_t ah[4], alr[4];
        ldmatrix_x4(ah,  su + OFF_AH + a_lane_off + k0 * 2);
        ldmatrix_x4(alr, su + OFF_AL + a_lane_off + k0 * 2);
        #pragma unroll
        for (int n = 0; n < NT; n++) {
            uint32_t bh[2], bl[2];
            uint32_t boff = b_lane_off + (uint32_t)(n * 8 * LD * 2) + k0 * 2;
            ldmatrix_x2(bh, su + OFF_BH + boff);
            ldmatrix_x2(bl, su + OFF_BL + boff);
            mma_bf16(acc[n], ah, bh);
            mma_bf16(acc[n], ah, bl);
            mma_bf16(acc[n], alr, bh);
        }
    }

    const int r0 = rowBase + warp_r * 16 + (lane >> 2);
    const int r1 = r0 + 8;
    #pragma unroll
    for (int n = 0; n < NT; n++) {
        const int col = warp_c * (BN / 2) + n * 8 + (lane & 3) * 2;
        const float bx = bias[col], by = bias[col + 1];
        if (PQ_MODE) {
            const float a0 = al[col], a1 = al[col + 1];
            if (r0 < N_NODES) {
                float h0v = acc[n][0] + bx, h1v = acc[n][1] + by;
                float P0 = __expf(a0 * h0v), P1 = __expf(a1 * h1v);
                __half2 x0 = __floats2half2_rn(P0, P0 * h0v);
                __half2 x1 = __floats2half2_rn(P1, P1 * h1v);
                uint2 u; u.x = *(uint32_t*)&x0; u.y = *(uint32_t*)&x1;
                *(uint2*)(g_pq + (size_t)r0 * 128 + col) = u;
            }
            if (r1 < N_NODES) {
                float h0v = acc[n][2] + bx, h1v = acc[n][3] + by;
                float P0 = __expf(a0 * h0v), P1 = __expf(a1 * h1v);
                __half2 x0 = __floats2half2_rn(P0, P0 * h0v);
                __half2 x1 = __floats2half2_rn(P1, P1 * h1v);
                uint2 u; u.x = *(uint32_t*)&x0; u.y = *(uint32_t*)&x1;
                *(uint2*)(g_pq + (size_t)r1 * 128 + col) = u;
            }
        } else {
            if (r0 < N_NODES)
                *(float2*)(Out + (size_t)r0 * BN + col) = make_float2(acc[n][0] + bx, acc[n][1] + by);
            if (r1 < N_NODES)
                *(float2*)(Out + (size_t)r1 * BN + col) = make_float2(acc[n][2] + bx, acc[n][3] + by);
        }
    }
}

// ---------------- aggregation: warp/node, gather-add over (P,Q) ----------------
__global__ void gat_agg_sum(float* __restrict__ out) {
    const int node = blockIdx.x * (blockDim.x >> 5) + (threadIdx.x >> 5);
    if (node >= N_NODES) return;
    const int lane = threadIdx.x & 31;
    const int beg = g_rowptr[node];
    const int end = g_rowptr[node + 1];

    float S0=0.f,S1=0.f,S2=0.f,S3=0.f;
    float A0=0.f,A1=0.f,A2=0.f,A3=0.f;

    const uint4* __restrict__ pq = (const uint4*)g_pq;
    #define ACCUM(v) do { \
        __half2 p0 = *(__half2*)&(v).x, p1 = *(__half2*)&(v).y; \
        __half2 p2 = *(__half2*)&(v).z, p3 = *(__half2*)&(v).w; \
        float2 f0 = __half22float2(p0), f1 = __half22float2(p1); \
        float2 f2 = __half22float2(p2), f3 = __half22float2(p3); \
        S0 += f0.x; A0 += f0.y;  S1 += f1.x; A1 += f1.y; \
        S2 += f2.x; A2 += f2.y;  S3 += f3.x; A3 += f3.y; \
    } while (0)

    int e = beg;
    for (; e + 4 <= end; e += 4) {
        int s0 = __ldg(&g_csrc[e + 0]);
        int s1 = __ldg(&g_csrc[e + 1]);
        int s2 = __ldg(&g_csrc[e + 2]);
        int s3 = __ldg(&g_csrc[e + 3]);
        uint4 v0 = pq[(size_t)s0 * 32 + lane];
        uint4 v1 = pq[(size_t)s1 * 32 + lane];
        uint4 v2 = pq[(size_t)s2 * 32 + lane];
        uint4 v3 = pq[(size_t)s3 * 32 + lane];
        ACCUM(v0); ACCUM(v1); ACCUM(v2); ACCUM(v3);
    }
    for (; e < end; e++) {
        int s = __ldg(&g_csrc[e]);
        uint4 v = pq[(size_t)s * 32 + lane];
        ACCUM(v);
    }
    #undef ACCUM

    float4 o;
    o.x = fmaxf(A0 / (S0 + EPS_F), 0.f);
    o.y = fmaxf(A1 / (S1 + EPS_F), 0.f);
    o.z = fmaxf(A2 / (S2 + EPS_F), 0.f);
    o.w = fmaxf(A3 / (S3 + EPS_F), 0.f);
    *(float4*)(out + (size_t)node * HCDIM + lane * 4) = o;
}

// ---------------- head: logits + log_softmax ----------------
__global__ void proj2_kernel(const float* __restrict__ Wp2, const float* __restrict__ bp2,
                             float* __restrict__ out) {
    __shared__ float w2[N_CLS * C_DIM];
    __shared__ float b2[N_CLS];
    __shared__ float ts[128][C_DIM + 1];

    const int tid = threadIdx.x;           // 128
    for (int i = tid; i < N_CLS * C_DIM; i += 128) w2[i] = Wp2[i];
    if (tid < N_CLS) b2[tid] = bp2[tid];

    const int nodeBase = blockIdx.x * 128;
    for (int i = tid; i < 128 * C_DIM; i += 128) {
        int r = i / C_DIM, c = i % C_DIM;
        int node = nodeBase + r;
        ts[r][c] = (node < N_NODES) ? g_t[(size_t)node * C_DIM + c] : 0.f;
    }
    __syncthreads();

    const int node = nodeBase + tid;
    if (node >= N_NODES) return;

    float logits[N_CLS];
    #pragma unroll
    for (int j = 0; j < N_CLS; j++) logits[j] = b2[j];
    #pragma unroll 4
    for (int k = 0; k < C_DIM; k++) {
        float tv = ts[tid][k];
        #pragma unroll
        for (int j = 0; j < N_CLS; j++) logits[j] += tv * w2[j * C_DIM + k];
    }

    float m = logits[0];
    #pragma unroll
    for (int j = 1; j < N_CLS; j++) m = fmaxf(m, logits[j]);
    float se = 0.f;
    #pragma unroll
    for (int j = 0; j < N_CLS; j++) se += __expf(logits[j] - m);
    float lse = m + __logf(se);
    #pragma unroll
    for (int j = 0; j < N_CLS; j++)
        out[(size_t)node * N_CLS + j] = logits[j] - lse;
}

// ---------------- launch ----------------
extern "C" void kernel_launch(void* const* d_in, const int* in_sizes, int n_in,
                              void* d_out, int out_size) {
    const float* x   = (const float*)d_in[0];
    const int*   ei  = (const int*)  d_in[1];
    const float* W0  = (const float*)d_in[2];
    const float* b0  = (const float*)d_in[3];
    const float* al0 = (const float*)d_in[4];
    const float* W1  = (const float*)d_in[6];
    const float* b1  = (const float*)d_in[7];
    const float* al1 = (const float*)d_in[8];
    const float* W2  = (const float*)d_in[10];
    const float* b2  = (const float*)d_in[11];
    const float* al2 = (const float*)d_in[12];
    const float* Wp1 = (const float*)d_in[14];
    const float* bp1 = (const float*)d_in[15];
    const float* Wp2 = (const float*)d_in[16];
    const float* bp2 = (const float*)d_in[17];
    float* out = (float*)d_out;

    const int* srcv = ei;
    const int* dstv = ei + N_EDGES;

    float *hin, *tb;
    __nv_bfloat16 *wh, *wl;
    cudaGetSymbolAddress((void**)&hin, g_hin);
    cudaGetSymbolAddress((void**)&tb, g_t);
    cudaGetSymbolAddress((void**)&wh, g_wh);
    cudaGetSymbolAddress((void**)&wl, g_wl);

    constexpr int LD = 136;
    const int SMEM128 = (2 * 64 * LD + 2 * 128 * LD) * 2;   // 104448
    const int SMEM64  = (2 * 64 * LD + 2 * 64  * LD) * 2;   // 69632
    cudaFuncSetAttribute((const void*)hmma_gemm<128, true>,
                         cudaFuncAttributeMaxDynamicSharedMemorySize, SMEM128);
    cudaFuncSetAttribute((const void*)hmma_gemm<64, false>,
                         cudaFuncAttributeMaxDynamicSharedMemorySize, SMEM64);

    // CSR + weight conversion (3 launches)
    count_deg_convw_kernel<<<(N_EDGES + 255) / 256, 256>>>(dstv, W0, W1, W2, Wp1);
    scan_kernel<<<1, 1024>>>();
    scatter_kernel<<<(N_EDGES + 255) / 256, 256>>>(srcv, dstv);

    const int gemmGrid = (N_NODES + 63) / 64;     // 1563
    const int aggGrid  = (N_NODES + 7) / 8;

    // layer 0 (launch #4 -> ncu target)
    hmma_gemm<128, true><<<gemmGrid, 256, SMEM128>>>(x,   wh + WOFF_0, wl + WOFF_0, b0, al0, nullptr);
    gat_agg_sum<<<aggGrid, 256>>>(hin);
    // layer 1
    hmma_gemm<128, true><<<gemmGrid, 256, SMEM128>>>(hin, wh + WOFF_1, wl + WOFF_1, b1, al1, nullptr);
    gat_agg_sum<<<aggGrid, 256>>>(hin);
    // layer 2
    hmma_gemm<128, true><<<gemmGrid, 256, SMEM128>>>(hin, wh + WOFF_2, wl + WOFF_2, b2, al2, nullptr);
    gat_agg_sum<<<aggGrid, 256>>>(hin);
    // head
    hmma_gemm<64, false><<<gemmGrid, 256, SMEM64>>>(hin, wh + WOFF_P1, wl + WOFF_P1, bp1, nullptr, tb);
    proj2_kernel<<<(N_NODES + 127) / 128, 128>>>(Wp2, bp2, out);
}